// round 12
// baseline (speedup 1.0000x reference)
#include <cuda_runtime.h>
#include <cuda_bf16.h>
#include <cstdint>

#define N_NODES 50000
#define C_IN    256
#define C_OUT   256
#define D_DOM   25000
#define K_DOM   16
#define N_ROWS  (D_DOM * K_DOM)      // 400000 output rows

#define BM      128
#define BN      128
#define NCHUNK  16            // 16 K-chunks of 16 = K 256
#define NSTAGES 3
#define STAGE_BYTES 16384     // Ahi/Alo/Bhi/Blo, 4KB each
#define SM_A_HI 0
#define SM_A_LO 4096
#define SM_B_HI 8192
#define SM_B_LO 12288
#define SM_TILEBUF (NSTAGES * STAGE_BYTES)          // 49152
#define SM_TOTAL   (SM_TILEBUF + 65536)             // 114688
#define M_TILES ((N_NODES + BM - 1) / BM)    // 391
#define NT_HALVES (M_TILES * 2)              // 782
#define PGRID   296                          // persistent grid (2/SM on 148 SMs)
#define HIST_BLOCKS ((N_ROWS + 255) / 256)   // 1563

// ---------------- scratch (static device globals; no cudaMalloc) -----------
__device__ __align__(16) __nv_bfloat16  g_wt_hi[C_OUT * C_IN];
__device__ __align__(16) __nv_bfloat16  g_wt_lo[C_OUT * C_IN];
__device__ __align__(16) __nv_bfloat16  g_a_hi[(size_t)N_NODES * C_IN]; // 25.6MB
__device__ __align__(16) __nv_bfloat16  g_a_lo[(size_t)N_NODES * C_IN]; // 25.6MB
__device__ int g_dom_is32;
// inverse map: CSR, offsets contiguous per 1024-node scan block => each
// 128-node tile owns a contiguous g_pos range. entry = row | (node&127)<<19
__device__ unsigned g_cnt[N_NODES];
__device__ unsigned g_off[N_NODES];
__device__ unsigned g_cur[N_NODES];
__device__ unsigned g_pos[N_ROWS];
__device__ unsigned g_total;

// ---------------- helpers ---------------------------------------------------
__device__ __forceinline__ uint32_t smem_u32(const void* p) {
    uint32_t a;
    asm("{ .reg .u64 t; cvta.to.shared.u64 t, %1; cvt.u32.u64 %0, t; }"
        : "=r"(a) : "l"(p));
    return a;
}

__device__ __forceinline__ void cp16(uint32_t dst, const void* src, int sz) {
    asm volatile("cp.async.cg.shared.global [%0], [%1], 16, %2;"
                 :: "r"(dst), "l"(src), "r"(sz) : "memory");
}

#define CP_COMMIT() asm volatile("cp.async.commit_group;" ::: "memory")
#define CP_WAIT1()  asm volatile("cp.async.wait_group 1;" ::: "memory")

#define LDM4(r0, r1, r2, r3, addr) \
    asm volatile("ldmatrix.sync.aligned.m8n8.x4.shared.b16 {%0,%1,%2,%3}, [%4];" \
                 : "=r"(r0), "=r"(r1), "=r"(r2), "=r"(r3) : "r"(addr))

#define MMA16816(d, a, b) \
    asm volatile("mma.sync.aligned.m16n8k16.row.col.f32.bf16.bf16.f32 " \
                 "{%0,%1,%2,%3}, {%4,%5,%6,%7}, {%8,%9}, {%0,%1,%2,%3};" \
                 : "+f"((d)[0]), "+f"((d)[1]), "+f"((d)[2]), "+f"((d)[3]) \
                 : "r"((a)[0]), "r"((a)[1]), "r"((a)[2]), "r"((a)[3]), \
                   "r"((b)[0]), "r"((b)[1]))

__device__ __forceinline__ uint32_t pack_bf16(float a, float b) {
    __nv_bfloat16 ha = __float2bfloat16(a);
    __nv_bfloat16 hb = __float2bfloat16(b);
    return ((uint32_t)__bfloat16_as_ushort(hb) << 16) | __bfloat16_as_ushort(ha);
}

__device__ __forceinline__ void st_cs4(float4* p, float4 v) {
    asm volatile("st.global.cs.v4.f32 [%0], {%1,%2,%3,%4};"
                 :: "l"(p), "f"(v.x), "f"(v.y), "f"(v.z), "f"(v.w) : "memory");
}

__device__ __forceinline__ int load_dom(const void* domains, int r) {
    if (g_dom_is32) return __ldg((const int*)domains + r);
    return (int)__ldg((const long long*)domains + r);
}

// ---------------- kernel 1: detect dtype + zero counters -------------------
__global__ void detect_zero_kernel(const long long* __restrict__ dom) {
    int i = blockIdx.x * 256 + threadIdx.x;
    if (i < N_NODES) g_cnt[i] = 0;
    if (i == 0) g_total = 0;
    if (blockIdx.x == 0) {
        int bad = 0;
        for (int j = threadIdx.x; j < 2048; j += 256) {
            long long v = dom[j];
            if (v < 0 || v >= (long long)N_NODES) bad = 1;
        }
        bad = __syncthreads_or(bad);
        if (threadIdx.x == 0) g_dom_is32 = bad;
    }
}

// ---------------- kernel 2: A split + histogram + weff prep (fused) --------
__global__ __launch_bounds__(256)
void prep_a_hist_w_kernel(const float* __restrict__ x,
                          const float* __restrict__ sn,
                          const void* __restrict__ dom,
                          const float* __restrict__ w) {
    if (blockIdx.x < HIST_BLOCKS) {
        int r = blockIdx.x * 256 + threadIdx.x;
        if (r < N_ROWS) atomicAdd(&g_cnt[load_dom(dom, r)], 1u);
    }
    if (blockIdx.x < (C_IN * C_OUT) / 256) {
        int i = blockIdx.x * 256 + threadIdx.x;
        int n = i & (C_OUT - 1);
        int k = i >> 8;
        float v = w[k * C_OUT + n] + w[(k + C_IN) * C_OUT + n];
        __nv_bfloat16 h = __float2bfloat16(v);
        g_wt_hi[n * C_IN + k] = h;
        g_wt_lo[n * C_IN + k] = __float2bfloat16(v - __bfloat162float(h));
    }
    int idx = blockIdx.x * 256 + threadIdx.x;        // 0 .. N*64-1
    if (idx >= N_NODES * 64) return;
    int row = idx >> 6;
    int c4  = idx & 63;
    float s = __ldg(sn + row);
    float4 v = *(const float4*)(x + (size_t)row * C_IN + c4 * 4);
    v.x *= s; v.y *= s; v.z *= s; v.w *= s;
    __nv_bfloat16 h0 = __float2bfloat16(v.x);
    __nv_bfloat16 h1 = __float2bfloat16(v.y);
    __nv_bfloat16 h2 = __float2bfloat16(v.z);
    __nv_bfloat16 h3 = __float2bfloat16(v.w);
    uint2 hi, lo;
    hi.x = ((uint32_t)__bfloat16_as_ushort(h1) << 16) | __bfloat16_as_ushort(h0);
    hi.y = ((uint32_t)__bfloat16_as_ushort(h3) << 16) | __bfloat16_as_ushort(h2);
    lo.x = pack_bf16(v.x - __bfloat162float(h0), v.y - __bfloat162float(h1));
    lo.y = pack_bf16(v.z - __bfloat162float(h2), v.w - __bfloat162float(h3));
    *(uint2*)(g_a_hi + (size_t)row * C_IN + c4 * 4) = hi;
    *(uint2*)(g_a_lo + (size_t)row * C_IN + c4 * 4) = lo;
}

// ---------------- kernel 3: scan + alloc -----------------------------------
__global__ __launch_bounds__(1024)
void k_allocscan(void) {
    const int tid = threadIdx.x;
    const int i = blockIdx.x * 1024 + tid;
    unsigned v = (i < N_NODES) ? g_cnt[i] : 0;
    unsigned incl = v;
#pragma unroll
    for (int o = 1; o < 32; o <<= 1) {
        unsigned t = __shfl_up_sync(0xFFFFFFFFu, incl, o);
        if ((tid & 31) >= o) incl += t;
    }
    __shared__ unsigned wsum[32];
    __shared__ unsigned sbase;
    if ((tid & 31) == 31) wsum[tid >> 5] = incl;
    __syncthreads();
    if (tid < 32) {
        unsigned s = wsum[tid];
        unsigned is = s;
#pragma unroll
        for (int o = 1; o < 32; o <<= 1) {
            unsigned t = __shfl_up_sync(0xFFFFFFFFu, is, o);
            if (tid >= o) is += t;
        }
        wsum[tid] = is - s;
        if (tid == 31) sbase = atomicAdd(&g_total, is);
    }
    __syncthreads();
    unsigned excl = sbase + wsum[tid >> 5] + (incl - v);
    if (i < N_NODES) { g_off[i] = excl; g_cur[i] = excl; }
}

// ---------------- kernel 4: fill CSR (packed entries) ----------------------
__global__ void k_fill(const void* __restrict__ domains) {
    int r = blockIdx.x * 256 + threadIdx.x;
    if (r < N_ROWS) {
        int i = load_dom(domains, r);
        unsigned p = atomicAdd(&g_cur[i], 1u);
        g_pos[p] = (unsigned)r | ((unsigned)(i & 127) << 19);
    }
}

// ---------------- kernel 5: persistent GEMM + interleaved scatter ----------
extern __shared__ char dsm[];

__global__ __launch_bounds__(256, 2)
void zgemm_persist_kernel(const float* __restrict__ bias,
                          float4* __restrict__ out) {
    const int tid  = threadIdx.x;
    const int lane = tid & 31;
    const int wid  = tid >> 5;
    const uint32_t sb = smem_u32(dsm);
    char* sbufc = dsm + SM_TILEBUF;        // 64KB pending-tile buffer
    float* stile = (float*)sbufc;

    // compute-role constants (tile-independent)
    const int wm   = wid & 1;
    const int wn   = wid >> 1;
    const int lrow  = lane & 15;
    const int lhalf = lane >> 4;
    const int swz = (lrow >> 2) & 1;
    const uint32_t a_off = (uint32_t)(wm * 64 + lrow) * 32 + (uint32_t)(lhalf ^ swz) * 16;
    const uint32_t b_off = (uint32_t)(wn * 32 + lrow) * 32 + (uint32_t)(lhalf ^ swz) * 16;
    const int crow = tid >> 1;
    const int cseg = tid & 1;
    const uint32_t doff = crow * 32 + (uint32_t)(cseg ^ ((crow >> 2) & 1)) * 16;

    // pending-scatter state (per warp; uniform across lanes)
    unsigned ps_cur = 0, ps_end = 0, ps_qb = 0;

    for (int t = blockIdx.x; t < NT_HALVES; t += gridDim.x) {
        const int m0 = (t >> 1) * BM;
        const int n0 = (t & 1) * BN;

        const int gmA = m0 + crow;
        const int szA = (gmA < N_NODES) ? 16 : 0;
        const char* srcAhi = (const char*)(g_a_hi + (size_t)gmA * C_IN + cseg * 8);
        const char* srcAlo = (const char*)(g_a_lo + (size_t)gmA * C_IN + cseg * 8);
        const char* srcBhi = (const char*)(g_wt_hi + (size_t)(n0 + crow) * C_IN + cseg * 8);
        const char* srcBlo = (const char*)(g_wt_lo + (size_t)(n0 + crow) * C_IN + cseg * 8);

#define ISSUE_COPY(s, kc) do {                                   \
        uint32_t _sbase = sb + (uint32_t)(s) * STAGE_BYTES;      \
        int _go = (kc) * 32;                                     \
        cp16(_sbase + SM_A_HI + doff, srcAhi + _go, szA);        \
        cp16(_sbase + SM_A_LO + doff, srcAlo + _go, szA);        \
        cp16(_sbase + SM_B_HI + doff, srcBhi + _go, 16);         \
        cp16(_sbase + SM_B_LO + doff, srcBlo + _go, 16);         \
    } while (0)

        ISSUE_COPY(0, 0); CP_COMMIT();
        ISSUE_COPY(1, 1); CP_COMMIT();

        float acc[4][4][4];
#pragma unroll
        for (int mt = 0; mt < 4; mt++)
#pragma unroll
            for (int nt = 0; nt < 4; nt++)
#pragma unroll
                for (int j = 0; j < 4; j++) acc[mt][nt][j] = 0.0f;

        for (int kc = 0; kc < NCHUNK; kc++) {
            CP_WAIT1();
            __syncthreads();
            int pf = kc + NSTAGES - 1;
            if (pf < NCHUNK) ISSUE_COPY(pf % NSTAGES, pf);
            CP_COMMIT();

            // early: fetch up to 8 packed dup entries of the PENDING tile
            unsigned pk[8];
            const bool have = (ps_cur < ps_end);
            if (have) {
#pragma unroll
                for (int j = 0; j < 8; j++)
                    pk[j] = (ps_cur + j < ps_end) ? __ldg(&g_pos[ps_cur + j])
                                                  : 0xFFFFFFFFu;
            }

            const uint32_t st = sb + (uint32_t)(kc % NSTAGES) * STAGE_BYTES;
            uint32_t ah[4][4], bh[4][2], bl[4][2];
#pragma unroll
            for (int mt = 0; mt < 4; mt++)
                LDM4(ah[mt][0], ah[mt][1], ah[mt][2], ah[mt][3],
                     st + SM_A_HI + a_off + mt * 512);
#pragma unroll
            for (int ntp = 0; ntp < 2; ntp++) {
                uint32_t r0, r1, r2, r3;
                LDM4(r0, r1, r2, r3, st + SM_B_HI + b_off + ntp * 512);
                bh[ntp * 2][0] = r0; bh[ntp * 2][1] = r2;
                bh[ntp * 2 + 1][0] = r1; bh[ntp * 2 + 1][1] = r3;
                LDM4(r0, r1, r2, r3, st + SM_B_LO + b_off + ntp * 512);
                bl[ntp * 2][0] = r0; bl[ntp * 2][1] = r2;
                bl[ntp * 2 + 1][0] = r1; bl[ntp * 2 + 1][1] = r3;
            }
#pragma unroll
            for (int mt = 0; mt < 4; mt++)
#pragma unroll
                for (int nt = 0; nt < 4; nt++) {
                    MMA16816(acc[mt][nt], ah[mt], bh[nt]);
                    MMA16816(acc[mt][nt], ah[mt], bl[nt]);
                }
#pragma unroll
            for (int mt = 0; mt < 4; mt++)
                LDM4(ah[mt][0], ah[mt][1], ah[mt][2], ah[mt][3],
                     st + SM_A_LO + a_off + mt * 512);
#pragma unroll
            for (int mt = 0; mt < 4; mt++)
#pragma unroll
                for (int nt = 0; nt < 4; nt++)
                    MMA16816(acc[mt][nt], ah[mt], bh[nt]);

            // late: consume the fetched dup entries (LDG latency now covered)
            if (have) {
#pragma unroll
                for (int j = 0; j < 8; j++) {
                    if (pk[j] != 0xFFFFFFFFu) {
                        unsigned r  = pk[j] & 0x7FFFFu;
                        unsigned ln = pk[j] >> 19;
                        float4 v = *(float4*)(sbufc + ln * 512 + lane * 16);
                        st_cs4(out + (size_t)r * 64 + ps_qb, v);
                    }
                }
                ps_cur += 8;
            }
        }

        // drain leftover pending scatter
        while (ps_cur < ps_end) {
            unsigned pkx = __ldg(&g_pos[ps_cur]); ps_cur++;
            unsigned r  = pkx & 0x7FFFFu;
            unsigned ln = pkx >> 19;
            float4 v = *(float4*)(sbufc + ln * 512 + lane * 16);
            st_cs4(out + (size_t)r * 64 + ps_qb, v);
        }
        __syncthreads();                  // all warps done reading sbuf

        // stage acc (+bias) into sbuf as f32[128][128]
        {
            const int erow = lane >> 2;
            const int ecol = (lane & 3) * 2;
#pragma unroll
            for (int nt = 0; nt < 4; nt++) {
                int nl = wn * 32 + nt * 8 + ecol;
                float b0v = bias[n0 + nl];
                float b1v = bias[n0 + nl + 1];
#pragma unroll
                for (int mt = 0; mt < 4; mt++) {
                    int ml = wm * 64 + mt * 16 + erow;
                    stile[ml * 128 + nl]           = acc[mt][nt][0] + b0v;
                    stile[ml * 128 + nl + 1]       = acc[mt][nt][1] + b1v;
                    stile[(ml + 8) * 128 + nl]     = acc[mt][nt][2] + b0v;
                    stile[(ml + 8) * 128 + nl + 1] = acc[mt][nt][3] + b1v;
                }
            }
        }
        __syncthreads();                  // sbuf fully staged

        // set pending state = this tile's contiguous dup range, split 8 ways
        {
            const int lastn = (m0 + BM <= N_NODES) ? (m0 + BM - 1) : (N_NODES - 1);
            unsigned S = __ldg(&g_off[m0]);
            unsigned E = __ldg(&g_off[lastn]) + __ldg(&g_cnt[lastn]);
            unsigned pw = ((E - S) + 7) >> 3;
            unsigned s0 = S + (unsigned)wid * pw;
            unsigned e0 = s0 + pw;
            if (s0 > E) s0 = E;
            if (e0 > E) e0 = E;
            ps_cur = s0; ps_end = e0;
            ps_qb  = (unsigned)((n0 >> 2) + lane);
        }
#undef ISSUE_COPY
    }

    // final drain
    while (ps_cur < ps_end) {
        unsigned pkx = __ldg(&g_pos[ps_cur]); ps_cur++;
        unsigned r  = pkx & 0x7FFFFu;
        unsigned ln = pkx >> 19;
        float4 v = *(float4*)(sbufc + ln * 512 + lane * 16);
        st_cs4(out + (size_t)r * 64 + ps_qb, v);
    }
}

// ---------------- launch ---------------------------------------------------
extern "C" void kernel_launch(void* const* d_in, const int* in_sizes, int n_in,
                              void* d_out, int out_size) {
    const float* x   = (const float*)d_in[0];
    const float* sn  = (const float*)d_in[1];
    const void*  dom = d_in[2];
    const float* w   = (const float*)d_in[3];
    const float* b   = (const float*)d_in[4];

    cudaFuncSetAttribute(zgemm_persist_kernel,
                         cudaFuncAttributeMaxDynamicSharedMemorySize, SM_TOTAL);

    detect_zero_kernel<<<(N_NODES + 255) / 256, 256>>>((const long long*)dom);
    prep_a_hist_w_kernel<<<(N_NODES * 64 + 255) / 256, 256>>>(x, sn, dom, w);
    k_allocscan<<<(N_NODES + 1023) / 1024, 1024>>>();
    k_fill<<<(N_ROWS + 255) / 256, 256>>>(dom);

    zgemm_persist_kernel<<<PGRID, 256, SM_TOTAL>>>(b, (float4*)d_out);
}

// round 16
// speedup vs baseline: 1.0190x; 1.0190x over previous
#include <cuda_runtime.h>
#include <cuda_bf16.h>
#include <cstdint>

#define N_NODES 50000
#define C_IN    256
#define C_OUT   256
#define D_DOM   25000
#define K_DOM   16
#define N_ROWS  (D_DOM * K_DOM)      // 400000 output rows

#define BM      128
#define BN      128
#define NCHUNK  16            // 16 K-chunks of 16 = K 256
#define NSTAGES 4
#define STAGE_BYTES 16384     // Ahi/Alo/Bhi/Blo, 4KB each
#define SM_A_HI 0
#define SM_A_LO 4096
#define SM_B_HI 8192
#define SM_B_LO 12288
#define M_TILES ((N_NODES + BM - 1) / BM)    // 391
#define HIST_BLOCKS ((N_ROWS + 255) / 256)   // 1563

// ---------------- scratch (static device globals; no cudaMalloc) -----------
__device__ __align__(16) __nv_bfloat16  g_wt_hi[C_OUT * C_IN];
__device__ __align__(16) __nv_bfloat16  g_wt_lo[C_OUT * C_IN];
__device__ __align__(16) __nv_bfloat16  g_a_hi[(size_t)N_NODES * C_IN]; // 25.6MB
__device__ __align__(16) __nv_bfloat16  g_a_lo[(size_t)N_NODES * C_IN]; // 25.6MB
__device__ int g_dom_is32;
// inverse map (node -> output rows), CSR with atomic block allocation
__device__ unsigned g_cnt[N_NODES];
__device__ unsigned g_off[N_NODES];
__device__ unsigned g_cur[N_NODES];
__device__ unsigned g_pos[N_ROWS];
__device__ unsigned g_total;

// ---------------- helpers ---------------------------------------------------
__device__ __forceinline__ uint32_t smem_u32(const void* p) {
    uint32_t a;
    asm("{ .reg .u64 t; cvta.to.shared.u64 t, %1; cvt.u32.u64 %0, t; }"
        : "=r"(a) : "l"(p));
    return a;
}

__device__ __forceinline__ void cp16(uint32_t dst, const void* src, int sz) {
    asm volatile("cp.async.cg.shared.global [%0], [%1], 16, %2;"
                 :: "r"(dst), "l"(src), "r"(sz) : "memory");
}

#define CP_COMMIT() asm volatile("cp.async.commit_group;" ::: "memory")
#define CP_WAIT2()  asm volatile("cp.async.wait_group 2;" ::: "memory")
#define CP_WAIT0()  asm volatile("cp.async.wait_group 0;" ::: "memory")

#define LDM4(r0, r1, r2, r3, addr) \
    asm volatile("ldmatrix.sync.aligned.m8n8.x4.shared.b16 {%0,%1,%2,%3}, [%4];" \
                 : "=r"(r0), "=r"(r1), "=r"(r2), "=r"(r3) : "r"(addr))

#define MMA16816(d, a, b) \
    asm volatile("mma.sync.aligned.m16n8k16.row.col.f32.bf16.bf16.f32 " \
                 "{%0,%1,%2,%3}, {%4,%5,%6,%7}, {%8,%9}, {%0,%1,%2,%3};" \
                 : "+f"((d)[0]), "+f"((d)[1]), "+f"((d)[2]), "+f"((d)[3]) \
                 : "r"((a)[0]), "r"((a)[1]), "r"((a)[2]), "r"((a)[3]), \
                   "r"((b)[0]), "r"((b)[1]))

__device__ __forceinline__ uint32_t pack_bf16(float a, float b) {
    __nv_bfloat16 ha = __float2bfloat16(a);
    __nv_bfloat16 hb = __float2bfloat16(b);
    return ((uint32_t)__bfloat16_as_ushort(hb) << 16) | __bfloat16_as_ushort(ha);
}

__device__ __forceinline__ void st_cs4(float4* p, float4 v) {
    asm volatile("st.global.cs.v4.f32 [%0], {%1,%2,%3,%4};"
                 :: "l"(p), "f"(v.x), "f"(v.y), "f"(v.z), "f"(v.w) : "memory");
}

__device__ __forceinline__ int load_dom(const void* domains, int r) {
    if (g_dom_is32) return __ldg((const int*)domains + r);
    return (int)__ldg((const long long*)domains + r);
}

// ======== branch B (CSR) kernels ===========================================
__global__ void detect_zero_kernel(const long long* __restrict__ dom) {
    int i = blockIdx.x * 256 + threadIdx.x;
    if (i < N_NODES) g_cnt[i] = 0;
    if (i == 0) g_total = 0;
    if (blockIdx.x == 0) {
        int bad = 0;
        for (int j = threadIdx.x; j < 2048; j += 256) {
            long long v = dom[j];
            if (v < 0 || v >= (long long)N_NODES) bad = 1;
        }
        bad = __syncthreads_or(bad);
        if (threadIdx.x == 0) g_dom_is32 = bad;
    }
}

__global__ void k_hist(const void* __restrict__ domains) {
    int r = blockIdx.x * 256 + threadIdx.x;
    if (r < N_ROWS) atomicAdd(&g_cnt[load_dom(domains, r)], 1u);
}

__global__ __launch_bounds__(1024)
void k_allocscan(void) {
    const int tid = threadIdx.x;
    const int i = blockIdx.x * 1024 + tid;
    unsigned v = (i < N_NODES) ? g_cnt[i] : 0;
    unsigned incl = v;
#pragma unroll
    for (int o = 1; o < 32; o <<= 1) {
        unsigned t = __shfl_up_sync(0xFFFFFFFFu, incl, o);
        if ((tid & 31) >= o) incl += t;
    }
    __shared__ unsigned wsum[32];
    __shared__ unsigned sbase;
    if ((tid & 31) == 31) wsum[tid >> 5] = incl;
    __syncthreads();
    if (tid < 32) {
        unsigned s = wsum[tid];
        unsigned is = s;
#pragma unroll
        for (int o = 1; o < 32; o <<= 1) {
            unsigned t = __shfl_up_sync(0xFFFFFFFFu, is, o);
            if (tid >= o) is += t;
        }
        wsum[tid] = is - s;
        if (tid == 31) sbase = atomicAdd(&g_total, is);
    }
    __syncthreads();
    unsigned excl = sbase + wsum[tid >> 5] + (incl - v);
    if (i < N_NODES) { g_off[i] = excl; g_cur[i] = excl; }
}

__global__ void k_fill(const void* __restrict__ domains) {
    int r = blockIdx.x * 256 + threadIdx.x;
    if (r < N_ROWS) {
        int i = load_dom(domains, r);
        unsigned p = atomicAdd(&g_cur[i], 1u);
        g_pos[p] = (unsigned)r;
    }
}

// ======== branch A: A split + weff prep (fused) ============================
__global__ __launch_bounds__(256)
void prep_aw_kernel(const float* __restrict__ x,
                    const float* __restrict__ sn,
                    const float* __restrict__ w) {
    if (blockIdx.x < (C_IN * C_OUT) / 256) {
        int i = blockIdx.x * 256 + threadIdx.x;
        int n = i & (C_OUT - 1);
        int k = i >> 8;
        float v = w[k * C_OUT + n] + w[(k + C_IN) * C_OUT + n];
        __nv_bfloat16 h = __float2bfloat16(v);
        g_wt_hi[n * C_IN + k] = h;
        g_wt_lo[n * C_IN + k] = __float2bfloat16(v - __bfloat162float(h));
    }
    int idx = blockIdx.x * 256 + threadIdx.x;        // 0 .. N*64-1
    if (idx >= N_NODES * 64) return;
    int row = idx >> 6;
    int c4  = idx & 63;
    float s = __ldg(sn + row);
    float4 v = *(const float4*)(x + (size_t)row * C_IN + c4 * 4);
    v.x *= s; v.y *= s; v.z *= s; v.w *= s;
    __nv_bfloat16 h0 = __float2bfloat16(v.x);
    __nv_bfloat16 h1 = __float2bfloat16(v.y);
    __nv_bfloat16 h2 = __float2bfloat16(v.z);
    __nv_bfloat16 h3 = __float2bfloat16(v.w);
    uint2 hi, lo;
    hi.x = ((uint32_t)__bfloat16_as_ushort(h1) << 16) | __bfloat16_as_ushort(h0);
    hi.y = ((uint32_t)__bfloat16_as_ushort(h3) << 16) | __bfloat16_as_ushort(h2);
    lo.x = pack_bf16(v.x - __bfloat162float(h0), v.y - __bfloat162float(h1));
    lo.y = pack_bf16(v.z - __bfloat162float(h2), v.w - __bfloat162float(h3));
    *(uint2*)(g_a_hi + (size_t)row * C_IN + c4 * 4) = hi;
    *(uint2*)(g_a_lo + (size_t)row * C_IN + c4 * 4) = lo;
}

// ======== fused GEMM + scatter (R11 form, unchanged) =======================
extern __shared__ char dsm[];

__global__ __launch_bounds__(256)
void zgemm_scatter_kernel(const float* __restrict__ bias,
                          float4* __restrict__ out) {
    const int tid = threadIdx.x;
    const int m0 = (blockIdx.x >> 1) * BM;
    const int n0 = (blockIdx.x & 1) * BN;
    const uint32_t sb = smem_u32(dsm);

    const int crow = tid >> 1;
    const int cseg = tid & 1;
    const int gmA  = m0 + crow;
    const int szA  = (gmA < N_NODES) ? 16 : 0;
    const char* srcAhi = (const char*)(g_a_hi + (size_t)gmA * C_IN + cseg * 8);
    const char* srcAlo = (const char*)(g_a_lo + (size_t)gmA * C_IN + cseg * 8);
    const char* srcBhi = (const char*)(g_wt_hi + (size_t)(n0 + crow) * C_IN + cseg * 8);
    const char* srcBlo = (const char*)(g_wt_lo + (size_t)(n0 + crow) * C_IN + cseg * 8);
    const uint32_t doff = crow * 32 + (uint32_t)(cseg ^ ((crow >> 2) & 1)) * 16;

#define ISSUE_COPY(s, kc) do {                                   \
        uint32_t _sbase = sb + (uint32_t)(s) * STAGE_BYTES;      \
        int _go = (kc) * 32;                                     \
        cp16(_sbase + SM_A_HI + doff, srcAhi + _go, szA);        \
        cp16(_sbase + SM_A_LO + doff, srcAlo + _go, szA);        \
        cp16(_sbase + SM_B_HI + doff, srcBhi + _go, 16);         \
        cp16(_sbase + SM_B_LO + doff, srcBlo + _go, 16);         \
    } while (0)

    ISSUE_COPY(0, 0); CP_COMMIT();
    ISSUE_COPY(1, 1); CP_COMMIT();
    ISSUE_COPY(2, 2); CP_COMMIT();

    const int lane = tid & 31;
    const int wid  = tid >> 5;
    const int wm   = wid & 1;
    const int wn   = wid >> 1;
    const int lrow  = lane & 15;
    const int lhalf = lane >> 4;
    const int swz = (lrow >> 2) & 1;
    const uint32_t a_off = (uint32_t)(wm * 64 + lrow) * 32 + (uint32_t)(lhalf ^ swz) * 16;
    const uint32_t b_off = (uint32_t)(wn * 32 + lrow) * 32 + (uint32_t)(lhalf ^ swz) * 16;

    float acc[4][4][4];
#pragma unroll
    for (int mt = 0; mt < 4; mt++)
#pragma unroll
        for (int nt = 0; nt < 4; nt++)
#pragma unroll
            for (int j = 0; j < 4; j++) acc[mt][nt][j] = 0.0f;

    for (int kc = 0; kc < NCHUNK; kc++) {
        CP_WAIT2();
        __syncthreads();
        int pf = kc + NSTAGES - 1;
        if (pf < NCHUNK) ISSUE_COPY(pf & (NSTAGES - 1), pf);
        CP_COMMIT();

        const uint32_t st = sb + (uint32_t)(kc & (NSTAGES - 1)) * STAGE_BYTES;

        uint32_t ah[4][4], bh[4][2], bl[4][2];
#pragma unroll
        for (int mt = 0; mt < 4; mt++)
            LDM4(ah[mt][0], ah[mt][1], ah[mt][2], ah[mt][3],
                 st + SM_A_HI + a_off + mt * 512);
#pragma unroll
        for (int ntp = 0; ntp < 2; ntp++) {
            uint32_t r0, r1, r2, r3;
            LDM4(r0, r1, r2, r3, st + SM_B_HI + b_off + ntp * 512);
            bh[ntp * 2][0] = r0; bh[ntp * 2][1] = r2;
            bh[ntp * 2 + 1][0] = r1; bh[ntp * 2 + 1][1] = r3;
            LDM4(r0, r1, r2, r3, st + SM_B_LO + b_off + ntp * 512);
            bl[ntp * 2][0] = r0; bl[ntp * 2][1] = r2;
            bl[ntp * 2 + 1][0] = r1; bl[ntp * 2 + 1][1] = r3;
        }
#pragma unroll
        for (int mt = 0; mt < 4; mt++)
#pragma unroll
            for (int nt = 0; nt < 4; nt++) {
                MMA16816(acc[mt][nt], ah[mt], bh[nt]);
                MMA16816(acc[mt][nt], ah[mt], bl[nt]);
            }
#pragma unroll
        for (int mt = 0; mt < 4; mt++)
            LDM4(ah[mt][0], ah[mt][1], ah[mt][2], ah[mt][3],
                 st + SM_A_LO + a_off + mt * 512);
#pragma unroll
        for (int mt = 0; mt < 4; mt++)
#pragma unroll
            for (int nt = 0; nt < 4; nt++)
                MMA16816(acc[mt][nt], ah[mt], bh[nt]);
    }

    CP_WAIT0();
    __syncthreads();
    float* stile = (float*)dsm;            // 64KB = 128*128 f32
    const int erow = lane >> 2;
    const int ecol = (lane & 3) * 2;
#pragma unroll
    for (int nt = 0; nt < 4; nt++) {
        int nl = wn * 32 + nt * 8 + ecol;
        float b0v = bias[n0 + nl];
        float b1v = bias[n0 + nl + 1];
#pragma unroll
        for (int mt = 0; mt < 4; mt++) {
            int ml = wm * 64 + mt * 16 + erow;
            stile[ml * 128 + nl]           = acc[mt][nt][0] + b0v;
            stile[ml * 128 + nl + 1]       = acc[mt][nt][1] + b1v;
            stile[(ml + 8) * 128 + nl]     = acc[mt][nt][2] + b0v;
            stile[(ml + 8) * 128 + nl + 1] = acc[mt][nt][3] + b1v;
        }
    }
    __syncthreads();

    const int wrow0 = wid * 16;
#pragma unroll 1
    for (int rr = 0; rr < 16; rr++) {
        int node = m0 + wrow0 + rr;
        if (node >= N_NODES) break;
        unsigned start = __ldg(&g_off[node]);
        unsigned cnt   = __ldg(&g_cnt[node]);
        float4 v = *(float4*)(stile + (wrow0 + rr) * 128 + lane * 4);
#pragma unroll 1
        for (unsigned p = 0; p < cnt; p++) {
            unsigned r = __ldg(&g_pos[start + p]);
            st_cs4(out + (size_t)r * 64 + (n0 >> 2) + lane, v);
        }
    }
#undef ISSUE_COPY
}

// ---------------- launch: forked-stream graph capture ----------------------
extern "C" void kernel_launch(void* const* d_in, const int* in_sizes, int n_in,
                              void* d_out, int out_size) {
    const float* x   = (const float*)d_in[0];
    const float* sn  = (const float*)d_in[1];
    const void*  dom = d_in[2];
    const float* w   = (const float*)d_in[3];
    const float* b   = (const float*)d_in[4];

    cudaFuncSetAttribute(zgemm_scatter_kernel,
                         cudaFuncAttributeMaxDynamicSharedMemorySize,
                         NSTAGES * STAGE_BYTES);

    // Fork a side stream for the CSR chain; it overlaps with prep_aw on the
    // main stream and rejoins before the GEMM. All ops are graph-capturable
    // (kernel launches + event record/wait; no alloc, no sync).
    cudaStream_t s2;
    cudaEvent_t e1, e2;
    cudaStreamCreateWithFlags(&s2, cudaStreamNonBlocking);
    cudaEventCreateWithFlags(&e1, cudaEventDisableTiming);
    cudaEventCreateWithFlags(&e2, cudaEventDisableTiming);

    cudaEventRecord(e1, 0);
    cudaStreamWaitEvent(s2, e1, 0);

    // branch B (side stream): CSR inverse map
    detect_zero_kernel<<<(N_NODES + 255) / 256, 256, 0, s2>>>(
        (const long long*)dom);
    k_hist<<<(N_ROWS + 255) / 256, 256, 0, s2>>>(dom);
    k_allocscan<<<(N_NODES + 1023) / 1024, 1024, 0, s2>>>();
    k_fill<<<(N_ROWS + 255) / 256, 256, 0, s2>>>(dom);
    cudaEventRecord(e2, s2);

    // branch A (main stream): A split + weff prep
    prep_aw_kernel<<<(N_NODES * 64 + 255) / 256, 256>>>(x, sn, w);

    // join, then fused GEMM+scatter
    cudaStreamWaitEvent(0, e2, 0);
    zgemm_scatter_kernel<<<M_TILES * 2, 256, NSTAGES * STAGE_BYTES>>>(
        b, (float4*)d_out);
}